// round 16
// baseline (speedup 1.0000x reference)
#include <cuda_runtime.h>
#include <cuda_fp16.h>

// QuantumRegression: 12-wire state-vector sim, two samples per block packed
// into f32x2 lanes. 512 threads/CTA, 8 amps/thread (X[8],Y[8]) -> ~64 regs
// -> __launch_bounds__(512,2) -> 32 warps/SM (2x occupancy vs R14).
// Window MSB lives on lane bit t0 and rotates via __shfl_xor(.,1); tangent
// rotations are shfl-symmetric (X += tn*Y_partner; Y -= tn*X_partner).
// State in shared fp16: u64/amp = (X half2, Y half2); sw8(a) = a^nib1^nib2,
// injectivity re-proven for all six layouts (t0 placed at amp bit3 in P6 to
// avoid the low-nibble collision with T[0]).
//
// SIX-PASS schedule (algebra identical to verified R13/R14):
//  P1 init+rot1(w0-3)+diag1+stair1 store [A: bits11-8 = t0,j2,j1,j0]
//  P2 rot1(w4-7)+diag1+stair1+C34 fold   [B: bits7-4 = t0,j2,j1,j0; C34 ctl=t5]
//  P3 rot1(w8-11)+diag1+stair1+C78(in-reg, ctl=t1)+rot2(w8-11)+diag2
//     +rot3~(w8-11); t1-residual corrected at P4 load  [C: bits3-0]
//  P4 rot2(w4-7)+diag2+rot3~(w4-6)
//  P5 rot2(w0-3)+diag2+rot3~(w0-2)
//  P6 rot3~(w3),rot3~(w7)+fused S^2 measurement [bits8,7,4,3 = j2,j1,j0,t0]
// stair2/stair3 folded into S^2 measurement weights; tangent rotations with
// cosines deferred to diag tables / alpha3^2.

typedef unsigned long long u64;
#define NW 12

__device__ ulonglong2 g_gx[36];
__device__ ulonglong2 g_dtab[96];
__device__ float      g_a3;
__device__ float4     g_l0[12];

static __device__ __forceinline__ u64 pack2(float lo, float hi) {
    u64 r; asm("mov.b64 %0, {%1, %2};" : "=l"(r) : "f"(lo), "f"(hi)); return r;
}
static __device__ __forceinline__ float2 unpack2(u64 v) {
    float2 r; asm("mov.b64 {%0, %1}, %2;" : "=f"(r.x), "=f"(r.y) : "l"(v)); return r;
}
static __device__ __forceinline__ u64 dup2(float v) { return pack2(v, v); }
static __device__ __forceinline__ u64 fma2(u64 a, u64 b, u64 c) {
    u64 d; asm("fma.rn.f32x2 %0, %1, %2, %3;" : "=l"(d) : "l"(a), "l"(b), "l"(c)); return d;
}
static __device__ __forceinline__ u64 mul2(u64 a, u64 b) {
    u64 d; asm("mul.rn.f32x2 %0, %1, %2;" : "=l"(d) : "l"(a), "l"(b)); return d;
}
static __device__ __forceinline__ u64 neg2(u64 a) { return a ^ 0x8000000080000000ULL; }

static __device__ __forceinline__ u64 amp_pack(u64 X, u64 Y) {
    float2 x = unpack2(X), y = unpack2(Y);
    __half2 hx = __floats2half2_rn(x.x, x.y);
    __half2 hy = __floats2half2_rn(y.x, y.y);
    unsigned int ix = *reinterpret_cast<unsigned int*>(&hx);
    unsigned int iy = *reinterpret_cast<unsigned int*>(&hy);
    u64 r; asm("mov.b64 %0, {%1, %2};" : "=l"(r) : "r"(ix), "r"(iy));
    return r;
}
static __device__ __forceinline__ void amp_unpack(u64 v, u64& X, u64& Y) {
    unsigned int ix, iy;
    asm("mov.b64 {%0, %1}, %2;" : "=r"(ix), "=r"(iy) : "l"(v));
    float2 x = __half22float2(*reinterpret_cast<__half2*>(&ix));
    float2 y = __half22float2(*reinterpret_cast<__half2*>(&iy));
    X = pack2(x.x, x.y);
    Y = pack2(y.x, y.y);
}
static __device__ __forceinline__ u64 shfl64(u64 v) {
    return __shfl_xor_sync(0xFFFFFFFFu, v, 1);
}

__device__ __host__ __forceinline__ constexpr int tau4(int k) {
    int b3 = (k >> 3) & 1;
    int b2 = ((k >> 2) & 1) ^ b3;
    int b1 = ((k >> 1) & 1) ^ b2;
    int b0 = (k & 1) ^ b1;
    return (b3 << 3) | (b2 << 2) | (b1 << 1) | b0;
}
__device__ __host__ __forceinline__ constexpr int sw8(int a) {
    return a ^ ((a >> 4) & 0xF) ^ ((a >> 8) & 0xF);
}
__device__ __host__ __forceinline__ constexpr int offA(int v) { return (v << 8) ^ v; }
__device__ __host__ __forceinline__ constexpr int offB(int v) { return (v << 4) ^ v; }
__device__ __host__ __forceinline__ constexpr int off6(int j) {
    return ((j & 1) ? 0x11 : 0) ^ ((j & 2) ? 0x88 : 0) ^ ((j & 4) ? 0x101 : 0);
}

#define SM_ST   0        // u64 st[4096]                  : 32768
#define SM_G    32768    // ulonglong2 gx[36]             : 576
#define SM_D    33344    // ulonglong2 dtab[96]           : 1536
#define SM_V    34880    // ulonglong2 v[12][2]           : 384
#define SM_F    35264    // ulonglong2 F[16]              : 256
#define SM_HW   35520    // float hw[12]                  : 48
#define SM_RED  35568    // float2 red[16]                : 128
#define SM_A3   35696    // float                         : 4
#define SMEM_BYTES 35712

struct GX { u64 tn, ntn; };
static __device__ __forceinline__ GX load_gx(const ulonglong2* __restrict__ g) {
    GX r; ulonglong2 p = g[0]; r.tn = p.x; r.ntn = p.y; return r;
}
static __device__ __forceinline__ void rxp(const GX& G, u64* X, u64* Y, int i0, int i1) {
    u64 X0 = X[i0], Y0 = Y[i0], X1 = X[i1], Y1 = Y[i1];
    X[i0] = fma2(G.tn, Y1, X0);
    Y[i0] = fma2(G.ntn, X1, Y0);
    X[i1] = fma2(G.tn, Y0, X1);
    Y[i1] = fma2(G.ntn, X0, Y1);
}
template<int M, int MSB>
static __device__ __forceinline__ void rotl(const GX& G, u64* X, u64* Y) {
#pragma unroll
    for (int r = 0; r < 8; r++) if (!(r & MSB)) rxp(G, X, Y, r, r ^ M);
}
// shfl rotation: partner = (lane^1, r^M). Gathers precede updates (warp-sync).
template<int M>
static __device__ __forceinline__ void rots(const GX& G, u64* X, u64* Y) {
    if (M == 0) {
#pragma unroll
        for (int r = 0; r < 8; r++) {
            u64 yp = shfl64(Y[r]);
            u64 xp = shfl64(X[r]);
            X[r] = fma2(G.tn, yp, X[r]);
            Y[r] = fma2(G.ntn, xp, Y[r]);
        }
    } else {
#pragma unroll
        for (int r = 0; r < 8; r++) if (!(r & M)) {
            u64 ypa = shfl64(Y[r ^ M]);
            u64 xpa = shfl64(X[r ^ M]);
            u64 ypb = shfl64(Y[r]);
            u64 xpb = shfl64(X[r]);
            X[r]     = fma2(G.tn, ypa, X[r]);
            Y[r]     = fma2(G.ntn, xpa, Y[r]);
            X[r ^ M] = fma2(G.tn, ypb, X[r ^ M]);
            Y[r ^ M] = fma2(G.ntn, xpb, Y[r ^ M]);
        }
    }
}
static __device__ __forceinline__ void diag1e(ulonglong2 d, u64* X, u64* Y, int r) {
    u64 nx = fma2(d.x, X[r], neg2(mul2(d.y, Y[r])));
    u64 ny = fma2(d.x, Y[r], mul2(d.y, X[r]));
    X[r] = nx; Y[r] = ny;
}

__global__ void qsetup_kernel(const float* __restrict__ params,
                              const float* __restrict__ head_w)
{
    int t = threadIdx.x;
    if (t < 36) {
        float th = params[12 + t];
        float c, s; sincosf(0.5f * th, &s, &c);
        float tn = s / c;
        ulonglong2 e; e.x = dup2(tn); e.y = dup2(-tn);
        g_gx[t] = e;
    }
    if (t == 40) {
        float prod = 1.f;
#pragma unroll
        for (int w = 0; w < NW; w++) prod *= cosf(0.5f * params[36 + w]);
        g_a3 = prod * prod;
    }
    if (t >= 64 && t < 160) {
        int i = t - 64;
        int l = i / 48, p = (i % 48) / 16, m = i & 15;
        const float* th = params + (l + 1) * NW + 4 * p;
        float phi = 0.f, cprod = 1.f;
#pragma unroll
        for (int q = 0; q < 4; q++) {
            if ((m >> (3 - q)) & 1) phi += th[q];
            cprod *= cosf(0.5f * th[q]);
        }
        float cp, sp; sincosf(phi, &sp, &cp);
        ulonglong2 e; e.x = dup2(cprod * cp); e.y = dup2(cprod * sp);
        g_dtab[i] = e;
    }
    if (t >= 176 && t < 188) {
        int w = t - 176;
        float c0, s0; sincosf(0.5f * params[w], &s0, &c0);
        g_l0[w] = make_float4(c0, s0, c0 * c0 - s0 * s0, 2.f * s0 * c0);
    }
}

__global__ void __launch_bounds__(512, 2)
qsim12_kernel(const float* __restrict__ inputs,
              const float* __restrict__ head_w,
              const float* __restrict__ head_b,
              float* __restrict__ out)
{
    extern __shared__ char sm[];
    u64* st          = (u64*)(sm + SM_ST);
    ulonglong2* gx   = (ulonglong2*)(sm + SM_G);
    ulonglong2* dtab = (ulonglong2*)(sm + SM_D);
    ulonglong2* vtab = (ulonglong2*)(sm + SM_V);
    ulonglong2* Ftab = (ulonglong2*)(sm + SM_F);
    float* hw  = (float*)(sm + SM_HW);
    float2* red = (float2*)(sm + SM_RED);
    float* a3  = (float*)(sm + SM_A3);

    const int b = blockIdx.x;
    const int t = threadIdx.x;          // 9 bits
    const int t0 = t & 1;

    if (t < 36) gx[t] = g_gx[t];
    if (t >= 64 && t < 160) dtab[t - 64] = g_dtab[t - 64];
    if (t == 176) a3[0] = g_a3;
    if (t < NW) {
        int w = t;
        float4 l0 = g_l0[w];
        float c0 = l0.x, s0 = l0.y, cn = l0.z, sn = l0.w;
        float v0x[2], v0y[2], v1x[2], v1y[2];
#pragma unroll
        for (int j = 0; j < 2; j++) {
            float cy, sy; sincosf(0.5f * inputs[(2 * b + j) * NW + w], &sy, &cy);
            v0x[j] = c0 * cy;  v0y[j] = -s0 * sy;
            float zx = c0 * sy, zy = -s0 * cy;
            v1x[j] = cn * zx - sn * zy;
            v1y[j] = sn * zx + cn * zy;
        }
        ulonglong2 e0; e0.x = pack2(v0x[0], v0x[1]); e0.y = pack2(v0y[0], v0y[1]);
        ulonglong2 e1; e1.x = pack2(v1x[0], v1x[1]); e1.y = pack2(v1y[0], v1y[1]);
        vtab[(w << 1) | 0] = e0;
        vtab[(w << 1) | 1] = e1;
        hw[w] = head_w[w];
    }
    __syncthreads();

    if (t < 16) {                       // F[m], m = (c0,c1,c2,c3) wires 0..3
        int c0 = (t >> 3) & 1, c1 = (t >> 2) & 1, c2 = (t >> 1) & 1, c3 = t & 1;
        int b0 = c0, b1 = c1 ^ c0, b2 = c2 ^ c1, b3 = c3 ^ c2;
        ulonglong2 a = vtab[0 | b0];
        u64 PX = a.x, PY = a.y;
        int bb[3] = {b1, b2, b3};
#pragma unroll
        for (int w = 1; w <= 3; w++) {
            ulonglong2 q = vtab[(w << 1) | bb[w - 1]];
            u64 nx = fma2(PX, q.x, neg2(mul2(PY, q.y)));
            u64 ny = fma2(PX, q.y, mul2(PY, q.x));
            PX = nx; PY = ny;
        }
        ulonglong2 f; f.x = PX; f.y = PY; Ftab[t] = f;
    }

    // ---- bases: T = t>>1 (8 bits); window MSB = t0 ----
    const int T = t >> 1;
    const int baseA = sw8(T);                               // A: a = win<<8 | T
    const int baseB = sw8(((T >> 4) << 8) | (T & 0xF));     // B: a = Th<<8|win<<4|Tl
    const int baseC = sw8(T << 4);                          // C: a = T<<4 | win
    const int stA = baseA ^ (t0 ? 0xF0F : 0);               // P1 store (canonical)
    const int ldA = baseA ^ (t0 ? 0x808 : 0);               // A canonical base
    const int ldB = baseB ^ (t0 ? 0x88 : 0);                // B canonical base
    const int stB = baseB ^ ((t0 ^ ((t >> 5) & 1)) ? 0xFF : 0); // C34 ctl = t5
    const int ldC = baseC ^ (t0 ? 8 : 0);
    const int stC = baseC ^ (t0 ? 0xF : 0);                 // t1 residual left
    const int cx3 = ((t ^ (t >> 1)) & 1) ? 0xF : 0;         // t0^t1 (P3 diag2 idx)
    // P6: amp = t8,t7,t6 | j2 | j1 | t5,t4 | j0 | t0 | t3,t2,t1
    const int Tp6 = ((t & 0x1C0) << 3) | ((t & 0x30) << 1) | ((t >> 1) & 7);
    const int base6 = sw8(Tp6) ^ (t0 ? 8 : 0);
    const int m8 = t0 << 3;

    // ---- S^2 measurement partials; wire sources:
    // w0=t8 w1=t7 w2=t6 w3=j2 w4=j1 w5=t5 w6=t4 w7=j0 w8=t0 w9=t3 w10=t2 w11=t1
    float S0, SA, SB, SC;
    {
        float P100 = (__popc(t & 0x100) & 1) ? -1.f : 1.f;
        float P080 = (__popc(t & 0x080) & 1) ? -1.f : 1.f;
        float P140 = (__popc(t & 0x140) & 1) ? -1.f : 1.f;
        float P0A0 = (__popc(t & 0x0A0) & 1) ? -1.f : 1.f;
        float P150 = (__popc(t & 0x150) & 1) ? -1.f : 1.f;
        float P151 = (__popc(t & 0x151) & 1) ? -1.f : 1.f;
        float P155 = (__popc(t & 0x155) & 1) ? -1.f : 1.f;
        float P0A8 = (__popc(t & 0x0A8) & 1) ? -1.f : 1.f;
        float P0AA = (__popc(t & 0x0AA) & 1) ? -1.f : 1.f;
        S0 = hw[0] * P100 + hw[1] * P080 + hw[2] * P140;
        SA = hw[3] * P080 + hw[5] * P0A0;                                  // j2
        SB = hw[4] * P140 + hw[6] * P150 + hw[8] * P151 + hw[10] * P155;   // j1
        SC = hw[7] * P0A0 + hw[9] * P0A8 + hw[11] * P0AA;                  // j0^j2
    }
    __syncthreads();

    const ulonglong2* g1 = gx;
    const ulonglong2* g2 = gx + 12;
    const ulonglong2* g3 = gx + 24;
    const ulonglong2* d1 = dtab;
    const ulonglong2* d2 = dtab + 48;

    u64 X[8], Y[8];

    // ======== P1: init + rot1(w0-3) + diag1 + stair1 store ========
    // A layout wires: w0=t0(bit11) w1=j2 w2=j1 w3=j0; w4..w11 = t8..t1.
    {
        int b5 = ((t >> 7) ^ (t >> 8)) & 1, b6 = ((t >> 6) ^ (t >> 7)) & 1;
        int b7 = ((t >> 5) ^ (t >> 6)) & 1, b8 = ((t >> 4) ^ (t >> 5)) & 1;
        int b9 = ((t >> 3) ^ (t >> 4)) & 1, b10 = ((t >> 2) ^ (t >> 3)) & 1;
        int b11 = ((t >> 1) ^ (t >> 2)) & 1;
        ulonglong2 p5 = vtab[(5 << 1) | b5];
        u64 PX = p5.x, PY = p5.y;
        int bbv[6] = {b6, b7, b8, b9, b10, b11};
#pragma unroll
        for (int w = 6; w <= 11; w++) {
            ulonglong2 q = vtab[(w << 1) | bbv[w - 6]];
            u64 nx = fma2(PX, q.x, neg2(mul2(PY, q.y)));
            u64 ny = fma2(PX, q.y, mul2(PY, q.x));
            PX = nx; PY = ny;
        }
        int c4 = (t >> 8) & 1;          // wire-4 value = t8
        ulonglong2 q0 = vtab[(4 << 1) | c4];
        ulonglong2 q1 = vtab[(4 << 1) | (c4 ^ 1)];
        u64 R0X = fma2(PX, q0.x, neg2(mul2(PY, q0.y)));
        u64 R0Y = fma2(PX, q0.y, mul2(PY, q0.x));
        u64 R1X = fma2(PX, q1.x, neg2(mul2(PY, q1.y)));
        u64 R1Y = fma2(PX, q1.y, mul2(PY, q1.x));
#pragma unroll
        for (int r = 0; r < 8; r++) {   // b4 = c4 ^ c3, c3 = j0 = r&1
            ulonglong2 F = Ftab[m8 | r];
            u64 QX = (r & 1) ? R1X : R0X;
            u64 QY = (r & 1) ? R1Y : R0Y;
            X[r] = fma2(F.x, QX, neg2(mul2(F.y, QY)));
            Y[r] = fma2(F.x, QY, mul2(F.y, QX));
        }
        GX G0 = load_gx(g1);     rots<0>(G0, X, Y);
        GX G1 = load_gx(g1 + 1); rotl<4, 4>(G1, X, Y);
        GX G2 = load_gx(g1 + 2); rotl<2, 2>(G2, X, Y);
        GX G3 = load_gx(g1 + 3); rotl<1, 1>(G3, X, Y);
#pragma unroll
        for (int r = 0; r < 8; r++) {
            diag1e(d1[m8 | r], X, Y, r);
            st[stA ^ offA(tau4(r))] = amp_pack(X[r], Y[r]);
        }
    }
    __syncthreads();

    // ======== P2: rot1(w4-7) + diag1 + stair1 + C34 fold ========
    {
#pragma unroll
        for (int r = 0; r < 8; r++) amp_unpack(st[ldB ^ offB(r)], X[r], Y[r]);
        GX G4 = load_gx(g1 + 4); rots<0>(G4, X, Y);
        GX G5 = load_gx(g1 + 5); rotl<4, 4>(G5, X, Y);
        GX G6 = load_gx(g1 + 6); rotl<2, 2>(G6, X, Y);
        GX G7 = load_gx(g1 + 7); rotl<1, 1>(G7, X, Y);
#pragma unroll
        for (int r = 0; r < 8; r++) {
            diag1e(d1[16 + (m8 | r)], X, Y, r);
            st[stB ^ offB(tau4(r))] = amp_pack(X[r], Y[r]);
        }
    }
    __syncthreads();

    // ======== P3: rot1(w8-11)+diag1+stair1+C78+rot2(w8-11)+diag2+rot3~ ====
    {
#pragma unroll
        for (int r = 0; r < 8; r++) amp_unpack(st[ldC ^ r], X[r], Y[r]);
        GX G8  = load_gx(g1 + 8);  rots<0>(G8, X, Y);
        GX G9  = load_gx(g1 + 9);  rotl<4, 4>(G9, X, Y);
        GX G10 = load_gx(g1 + 10); rotl<2, 2>(G10, X, Y);
        GX G11 = load_gx(g1 + 11); rotl<1, 1>(G11, X, Y);
#pragma unroll
        for (int r = 0; r < 8; r++) diag1e(d1[32 + (m8 | r)], X, Y, r);
        // rot2 at final labels: masks 8,4,2,1 -> reg space (shfl|local): 
        GX H8  = load_gx(g2 + 8);  rots<4>(H8, X, Y);
        GX H9  = load_gx(g2 + 9);  rotl<6, 4>(H9, X, Y);
        GX H10 = load_gx(g2 + 10); rotl<3, 2>(H10, X, Y);
        GX H11 = load_gx(g2 + 11); rotl<1, 1>(H11, X, Y);
#pragma unroll
        for (int r = 0; r < 8; r++) diag1e(d2[32 + (tau4(r) ^ cx3)], X, Y, r);
        // rot3~ final masks 0xC,6,3,1 -> reg space:
        GX J8  = load_gx(g3 + 8);  rots<2>(J8, X, Y);
        GX J9  = load_gx(g3 + 9);  rotl<5, 4>(J9, X, Y);
        GX J10 = load_gx(g3 + 10); rotl<2, 2>(J10, X, Y);
        GX J11 = load_gx(g3 + 11); rotl<1, 1>(J11, X, Y);
#pragma unroll
        for (int r = 0; r < 8; r++)
            st[stC ^ tau4(r)] = amp_pack(X[r], Y[r]);
    }
    __syncthreads();

    // ======== P4: rot2(w4-7)+diag2+rot3~(w4-6) ========
    {
#pragma unroll
        for (int r = 0; r < 8; r++)    // correct P3's t1 residual (bit4 = j0)
            amp_unpack(st[ldB ^ offB(r) ^ ((r & 1) ? 0xF : 0)], X[r], Y[r]);
        GX H4 = load_gx(g2 + 4); rots<0>(H4, X, Y);
        GX H5 = load_gx(g2 + 5); rotl<4, 4>(H5, X, Y);
        GX H6 = load_gx(g2 + 6); rotl<2, 2>(H6, X, Y);
        GX H7 = load_gx(g2 + 7); rotl<1, 1>(H7, X, Y);
#pragma unroll
        for (int r = 0; r < 8; r++) diag1e(d2[16 + (m8 | r)], X, Y, r);
        GX J4 = load_gx(g3 + 4); rots<4>(J4, X, Y);        // {t0,j2}
        GX J5 = load_gx(g3 + 5); rotl<6, 4>(J5, X, Y);     // {j2,j1}
        GX J6 = load_gx(g3 + 6); rotl<3, 2>(J6, X, Y);     // {j1,j0}
#pragma unroll
        for (int r = 0; r < 8; r++)
            st[ldB ^ offB(r)] = amp_pack(X[r], Y[r]);      // canonical
    }
    __syncthreads();

    // ======== P5: rot2(w0-3)+diag2+rot3~(w0-2) ========
    {
#pragma unroll
        for (int r = 0; r < 8; r++) amp_unpack(st[ldA ^ offA(r)], X[r], Y[r]);
        GX H0 = load_gx(g2);     rots<0>(H0, X, Y);
        GX H1 = load_gx(g2 + 1); rotl<4, 4>(H1, X, Y);
        GX H2 = load_gx(g2 + 2); rotl<2, 2>(H2, X, Y);
        GX H3 = load_gx(g2 + 3); rotl<1, 1>(H3, X, Y);
#pragma unroll
        for (int r = 0; r < 8; r++) diag1e(d2[m8 | r], X, Y, r);
        GX J0 = load_gx(g3);     rots<4>(J0, X, Y);        // {t0,j2}
        GX J1 = load_gx(g3 + 1); rotl<6, 4>(J1, X, Y);     // {j2,j1}
        GX J2 = load_gx(g3 + 2); rotl<3, 2>(J2, X, Y);     // {j1,j0}
#pragma unroll
        for (int r = 0; r < 8; r++)
            st[ldA ^ offA(r)] = amp_pack(X[r], Y[r]);
    }
    __syncthreads();

    // ======== P6: rot3~(w3), rot3~(w7) + fused S^2 measurement ========
    float p0 = 0.f, p1 = 0.f;
    {
#pragma unroll
        for (int r = 0; r < 8; r++) amp_unpack(st[base6 ^ off6(r)], X[r], Y[r]);
        GX J3 = load_gx(g3 + 3); rotl<6, 4>(J3, X, Y);     // w3~: {j2,j1}
        GX J7 = load_gx(g3 + 7); rots<1>(J7, X, Y);        // w7~: {j0,t0}
#pragma unroll
        for (int r = 0; r < 8; r++) {
            float wl = S0
                + (((r >> 2) & 1) ? -SA : SA)
                + (((r >> 1) & 1) ? -SB : SB)
                + (((r ^ (r >> 2)) & 1) ? -SC : SC);
            u64 U = fma2(X[r], X[r], mul2(Y[r], Y[r]));
            float2 u = unpack2(U);
            p0 = fmaf(u.x, wl, p0);
            p1 = fmaf(u.y, wl, p1);
        }
    }

    // ---- reduce 512 threads; apply deferred layer-3 scale ----
#pragma unroll
    for (int o = 16; o; o >>= 1) {
        p0 += __shfl_xor_sync(0xFFFFFFFFu, p0, o);
        p1 += __shfl_xor_sync(0xFFFFFFFFu, p1, o);
    }
    if ((t & 31) == 0) red[t >> 5] = make_float2(p0, p1);
    __syncthreads();
    if (t < 2) {
        float s = 0.f;
#pragma unroll
        for (int w = 0; w < 16; w++) s += (t == 0) ? red[w].x : red[w].y;
        out[2 * b + t] = s * a3[0] + head_b[0];
    }
}

extern "C" void kernel_launch(void* const* d_in, const int* in_sizes, int n_in,
                              void* d_out, int out_size)
{
    const float* inputs = (const float*)d_in[0];
    const float* params = (const float*)d_in[1];
    const float* head_w = (const float*)d_in[2];
    const float* head_b = (const float*)d_in[3];
    float* out = (float*)d_out;

    cudaFuncSetAttribute(qsim12_kernel, cudaFuncAttributeMaxDynamicSharedMemorySize, SMEM_BYTES);
    qsetup_kernel<<<1, 192>>>(params, head_w);
    int B2 = out_size / 2;
    qsim12_kernel<<<B2, 512, SMEM_BYTES>>>(inputs, head_w, head_b, out);
}

// round 17
// speedup vs baseline: 1.1964x; 1.1964x over previous
#include <cuda_runtime.h>
#include <cuda_fp16.h>

// QuantumRegression: 12-wire state-vector sim, two samples per block packed
// into f32x2 lanes. Registers/math are fp32 (f32x2); the SHARED state is
// stored fp16: one u64 per amp = (X half2, Y half2) = 8 bytes.
// Storage index sw8(a) = a ^ ((a>>4)&0xF) ^ ((a>>8)&0xF), conflict-free for
// every pass layout at LDS.64 16-lane phase granularity.  [R14 base]
//
// SIX-PASS schedule via CNOT-chain conjugation (verified R13/R14 algebra):
//  - Layer 0 folded into closed-form product-state init (prefix parity).
//  - stair2/stair3 deferred into measurement weights (S^2 parity sets).
//  - Layer-3 RX conjugated through stair2: rot3~(w) = exp(-i th/2 X_w X_{w+1}).
//  - P1: init + rot1(w0-3)+diag1+stair1 store            [res bits 11-8]
//  - P2: rot1(w4-7)+diag1+stair1+C34 store fold           [res bits 7-4]
//  - P3: rot1(w8-10)+diag1+stair1+C78(in-reg)+rot2(w8-11)
//        +diag2+rot3~(w8-11); residual folded into P4 load [res bits 3-0]
//  - P4: rot2(w4-7)+diag2+rot3~(w4-6)                     [res bits 7-4]
//  - P5: rot2(w0-3)+diag2+rot3~(w0-2)                     [res bits 11-8]
//  - P6: rot3~(w3),rot3~(w7) + fused S^2 measurement      [res bits 8,7,4,3]
//  Tangent rotations; dropped cosines -> diag tables / alpha3^2 scalar.
//
// THIS ROUND (consolidation on the 353us R14):
//  1. Single setup barrier: threads 16-31 compute the F table directly from
//     g_l0 + inputs (independent of vtab writes), removing one syncthreads.
//  2. rot1(w11) folded into the init product vector v11 (it commutes back
//     through the layer-0 staircase as the target of C(10,11) and flips only
//     b11 in prefix-parity coords). Its cosine is excluded from diag1(C)'s
//     prod(c) in qsetup; P3 loses one rotation.

typedef unsigned long long u64;

#define NW 12

// ---- batch-shared constant staging (written by qsetup_kernel) ----
__device__ ulonglong2 g_gx[36];      // tangent gates (tn, -tn) layers 1..3
__device__ ulonglong2 g_dtab[96];    // diag*prod(c) tables, layers 1..2
__device__ float      g_a3;          // layer-3 prod(c)^2
__device__ float4     g_l0[12];      // per-wire layer-0: c0, s0, cos(th), sin(th)
__device__ float2     g_rx11;        // layer-1 wire-11 RX: (cos, sin)

// ---- packed f32x2 helpers ----
static __device__ __forceinline__ u64 pack2(float lo, float hi) {
    u64 r; asm("mov.b64 %0, {%1, %2};" : "=l"(r) : "f"(lo), "f"(hi)); return r;
}
static __device__ __forceinline__ float2 unpack2(u64 v) {
    float2 r; asm("mov.b64 {%0, %1}, %2;" : "=f"(r.x), "=f"(r.y) : "l"(v)); return r;
}
static __device__ __forceinline__ u64 dup2(float v) { return pack2(v, v); }
static __device__ __forceinline__ u64 fma2(u64 a, u64 b, u64 c) {
    u64 d; asm("fma.rn.f32x2 %0, %1, %2, %3;" : "=l"(d) : "l"(a), "l"(b), "l"(c)); return d;
}
static __device__ __forceinline__ u64 mul2(u64 a, u64 b) {
    u64 d; asm("mul.rn.f32x2 %0, %1, %2;" : "=l"(d) : "l"(a), "l"(b)); return d;
}
static __device__ __forceinline__ u64 neg2(u64 a) { return a ^ 0x8000000080000000ULL; }

// ---- fp16 amp pack/unpack (state storage only; math stays fp32) ----
static __device__ __forceinline__ u64 amp_pack(u64 X, u64 Y) {
    float2 x = unpack2(X), y = unpack2(Y);
    __half2 hx = __floats2half2_rn(x.x, x.y);
    __half2 hy = __floats2half2_rn(y.x, y.y);
    unsigned int ix = *reinterpret_cast<unsigned int*>(&hx);
    unsigned int iy = *reinterpret_cast<unsigned int*>(&hy);
    u64 r; asm("mov.b64 %0, {%1, %2};" : "=l"(r) : "r"(ix), "r"(iy));
    return r;
}
static __device__ __forceinline__ void amp_unpack(u64 v, u64& X, u64& Y) {
    unsigned int ix, iy;
    asm("mov.b64 {%0, %1}, %2;" : "=r"(ix), "=r"(iy) : "l"(v));
    float2 x = __half22float2(*reinterpret_cast<__half2*>(&ix));
    float2 y = __half22float2(*reinterpret_cast<__half2*>(&iy));
    X = pack2(x.x, x.y);
    Y = pack2(y.x, y.y);
}

// staircase CNOT permutation on 4 bits (GF2-linear)
__device__ __host__ __forceinline__ constexpr int tau4(int k) {
    int b3 = (k >> 3) & 1;
    int b2 = ((k >> 2) & 1) ^ b3;
    int b1 = ((k >> 1) & 1) ^ b2;
    int b0 = (k & 1) ^ b1;
    return (b3 << 3) | (b2 << 2) | (b1 << 1) | b0;
}

// sw8 images of the k-part for each pass layout (compile-time)
__device__ __host__ __forceinline__ constexpr int offkA(int k) { return (k << 8) ^ k; }
__device__ __host__ __forceinline__ constexpr int offkB(int k) { return (k << 4) ^ k; }
__device__ __host__ __forceinline__ constexpr int offk6(int k) {
    int K = (((k >> 3) & 1) << 8) | (((k >> 2) & 1) << 7)
          | (((k >> 1) & 1) << 4) | ((k & 1) << 3);
    return K ^ ((K >> 4) & 0xF) ^ ((K >> 8) & 0xF);
}

// ---- shared memory layout (bytes) ----
#define SM_ST   0        // u64 st[4096] (fp16x4 amps)     : 32768
#define SM_G    32768    // ulonglong2 gx[3*12] (tn,-tn)   : 576
#define SM_D    33344    // ulonglong2 dtab[2*3*16]        : 1536
#define SM_V    34880    // ulonglong2 v[12][2]            : 384
#define SM_F    35264    // ulonglong2 F[16]               : 256
#define SM_HW   35520    // float hw[12]                   : 48
#define SM_RED  35568    // float2 red[8]                  : 64
#define SM_A3   35632    // float alpha3sq                 : 4
#define SMEM_BYTES 35648

// ---- tangent-form gate bundle ----
struct GX { u64 tn, ntn; };
static __device__ __forceinline__ GX load_gx(const ulonglong2* __restrict__ g) {
    GX r; ulonglong2 p = g[0]; r.tn = p.x; r.ntn = p.y; return r;
}

// tangent-form rotation on pair (i0, i1): 4 FMAs (scale c deferred)
static __device__ __forceinline__ void rxp(const GX& G, u64* X, u64* Y, int i0, int i1) {
    u64 X0 = X[i0], Y0 = Y[i0], X1 = X[i1], Y1 = Y[i1];
    X[i0] = fma2(G.tn, Y1, X0);
    Y[i0] = fma2(G.ntn, X1, Y0);
    X[i1] = fma2(G.tn, Y0, X1);
    Y[i1] = fma2(G.ntn, X0, Y1);
}

// rotation over all 16 regs with pair mask M (each pair once via MSB test)
template<int M, int MSB>
static __device__ __forceinline__ void rotm(const GX& G, u64* X, u64* Y) {
#pragma unroll
    for (int k = 0; k < 16; k++) if (!(k & MSB)) rxp(G, X, Y, k, k ^ M);
}

// apply diagonal entry d to slot k
static __device__ __forceinline__ void diag1e(ulonglong2 d, u64* X, u64* Y, int k) {
    u64 nx = fma2(d.x, X[k], neg2(mul2(d.y, Y[k])));
    u64 ny = fma2(d.x, Y[k], mul2(d.y, X[k]));
    X[k] = nx; Y[k] = ny;
}

// layer-0 v-vector for one wire/branch, both samples (from g_l0 + input trig)
static __device__ __forceinline__ void l0_vec(float4 l0, float cy0, float sy0,
                                              float cy1, float sy1, int bbit,
                                              u64& VX, u64& VY) {
    float c0 = l0.x, s0 = l0.y, cn = l0.z, sn = l0.w;
    float vx0, vy0, vx1, vy1;
    if (!bbit) {
        vx0 = c0 * cy0; vy0 = -s0 * sy0;
        vx1 = c0 * cy1; vy1 = -s0 * sy1;
    } else {
        float zx0 = c0 * sy0, zy0 = -s0 * cy0;
        float zx1 = c0 * sy1, zy1 = -s0 * cy1;
        vx0 = cn * zx0 - sn * zy0; vy0 = sn * zx0 + cn * zy0;
        vx1 = cn * zx1 - sn * zy1; vy1 = sn * zx1 + cn * zy1;
    }
    VX = pack2(vx0, vx1);
    VY = pack2(vy0, vy1);
}

// ---- pre-kernel: batch-shared constants, one block ----
__global__ void qsetup_kernel(const float* __restrict__ params,
                              const float* __restrict__ head_w)
{
    int t = threadIdx.x;
    if (t < 36) {                      // tangent coeffs: layer 1+t/12, wire t%12
        float th = params[12 + t];
        float c, s; sincosf(0.5f * th, &s, &c);
        float tn = s / c;
        ulonglong2 e; e.x = dup2(tn); e.y = dup2(-tn);
        g_gx[t] = e;
    }
    if (t == 40) {                     // layer-3 scalar: prod(c)^2
        float prod = 1.f;
#pragma unroll
        for (int w = 0; w < NW; w++) prod *= cosf(0.5f * params[36 + w]);
        g_a3 = prod * prod;
    }
    if (t == 41) {                     // layer-1 wire-11 RX folded into init
        float c, s; sincosf(0.5f * params[12 + 11], &s, &c);
        g_rx11 = make_float2(c, s);
    }
    if (t >= 64 && t < 160) {          // diag tables: prod(c) * e^{i sum th_w bit_w}
        int i = t - 64;                // layer = i/48 (0->L1), window = (i%48)/16, m = i&15
        int l = i / 48, p = (i % 48) / 16, m = i & 15;
        const float* th = params + (l + 1) * NW + 4 * p;
        float phi = 0.f, cprod = 1.f;
#pragma unroll
        for (int q = 0; q < 4; q++) {
            if ((m >> (3 - q)) & 1) phi += th[q];
            // w11's rot1 cosine lives in the init now (l==0, window 2, q==3)
            if (!(l == 0 && p == 2 && q == 3)) cprod *= cosf(0.5f * th[q]);
        }
        float cp, sp; sincosf(phi, &sp, &cp);
        ulonglong2 e; e.x = dup2(cprod * cp); e.y = dup2(cprod * sp);
        g_dtab[i] = e;
    }
    if (t >= 176 && t < 188) {         // layer-0 per-wire param trig
        int w = t - 176;
        float c0, s0; sincosf(0.5f * params[w], &s0, &c0);
        g_l0[w] = make_float4(c0, s0, c0 * c0 - s0 * s0, 2.f * s0 * c0);
    }
}

__global__ void __launch_bounds__(256, 2)
qsim13_kernel(const float* __restrict__ inputs,
              const float* __restrict__ head_w,
              const float* __restrict__ head_b,
              float* __restrict__ out)
{
    extern __shared__ char sm[];
    u64* st          = (u64*)(sm + SM_ST);
    ulonglong2* gx   = (ulonglong2*)(sm + SM_G);
    ulonglong2* dtab = (ulonglong2*)(sm + SM_D);
    ulonglong2* vtab = (ulonglong2*)(sm + SM_V);
    ulonglong2* Ftab = (ulonglong2*)(sm + SM_F);
    float* hw  = (float*)(sm + SM_HW);
    float2* red = (float2*)(sm + SM_RED);
    float* a3  = (float*)(sm + SM_A3);

    const int b = blockIdx.x;
    const int t = threadIdx.x;

    // ---- single setup phase: constants + per-sample trig + inline F table ----
    if (t >= 36 && t < 72) gx[t - 36] = g_gx[t - 36];
    if (t >= 64 && t < 160) dtab[t - 64] = g_dtab[t - 64];
    if (t == 160) a3[0] = g_a3;
    if (t < NW) {                      // layer-0 per-wire 2-vectors (both samples)
        int w = t;
        float cy0, sy0, cy1, sy1;
        sincosf(0.5f * inputs[(2 * b) * NW + w],     &sy0, &cy0);
        sincosf(0.5f * inputs[(2 * b + 1) * NW + w], &sy1, &cy1);
        float4 l0 = g_l0[w];
        u64 V0X, V0Y, V1X, V1Y;
        l0_vec(l0, cy0, sy0, cy1, sy1, 0, V0X, V0Y);
        l0_vec(l0, cy0, sy0, cy1, sy1, 1, V1X, V1Y);
        if (w == 11) {                 // fold layer-1 RX(w11) into v11
            float2 rc = g_rx11;
            u64 c = dup2(rc.x), s = dup2(rc.y);
            // v'[b] = c*v[b] - i s*v[b^1];  -i(X+iY) = Y - iX
            u64 n0X = fma2(c, V0X, mul2(s, V1Y));
            u64 n0Y = fma2(c, V0Y, neg2(mul2(s, V1X)));
            u64 n1X = fma2(c, V1X, mul2(s, V0Y));
            u64 n1Y = fma2(c, V1Y, neg2(mul2(s, V0X)));
            V0X = n0X; V0Y = n0Y; V1X = n1X; V1Y = n1Y;
        }
        ulonglong2 e0; e0.x = V0X; e0.y = V0Y;
        ulonglong2 e1; e1.x = V1X; e1.y = V1Y;
        vtab[(w << 1) | 0] = e0;
        vtab[(w << 1) | 1] = e1;
        hw[w] = head_w[w];
    }
    if (t >= 16 && t < 32) {           // F table inline (independent of vtab)
        int m = t - 16;
        int c0 = (m >> 3) & 1, c1 = (m >> 2) & 1, c2 = (m >> 1) & 1, c3 = m & 1;
        int bb[4] = {c0, c1 ^ c0, c2 ^ c1, c3 ^ c2};
        u64 PX = dup2(1.f), PY = 0ULL;
#pragma unroll
        for (int w = 0; w < 4; w++) {
            float cy0, sy0, cy1, sy1;
            sincosf(0.5f * inputs[(2 * b) * NW + w],     &sy0, &cy0);
            sincosf(0.5f * inputs[(2 * b + 1) * NW + w], &sy1, &cy1);
            u64 QX, QY;
            l0_vec(g_l0[w], cy0, sy0, cy1, sy1, bb[w], QX, QY);
            u64 nx = fma2(PX, QX, neg2(mul2(PY, QY)));
            u64 ny = fma2(PX, QY, mul2(PY, QX));
            PX = nx; PY = ny;
        }
        ulonglong2 f; f.x = PX; f.y = PY; Ftab[m] = f;
    }

    // ---- per-thread bases under sw8 (verified R14 maps) ----
    const int hi = t >> 4, lo = t & 15;
    const int baseA8  = t ^ hi;                           // res 11-8 (P1, P5)
    const int baseB8  = (hi << 8) | (lo ^ hi);            // res 7-4  (P2, P4)
    const int baseBs8 = baseB8 ^ ((hi & 1) ? 0xFF : 0);   // C34 fold (P2 store)
    const int baseC8  = (t << 4) ^ lo ^ hi;               // res 3-0  (P3)
    // P6 map: amp = t3<<11|t7<<10|t6<<9|k3<<8|k2<<7|t5<<6|t4<<5|k1<<4|k0<<3|t[2:0]
    const int T6 = (((t >> 3) & 1) << 11) | (((t >> 7) & 1) << 10) | (((t >> 6) & 1) << 9)
                 | (((t >> 5) & 1) << 6)  | (((t >> 4) & 1) << 5)  | (t & 7);
    const int base6 = T6 ^ ((T6 >> 4) & 0xF) ^ ((T6 >> 8) & 0xF);
    const int cxC = (t & 1) ? 0xF : 0;                    // C78_l1 in-reg (P3)

    __syncthreads();   // the ONLY setup barrier

    // ---- S^2 measurement weight partials (P6 wire<->bit sources) ----
    // wires: 0=t3 1=t7 2=t6 3=k3 4=k2 5=t5 6=t4 7=k1 8=k0 9=t2 10=t1 11=t0
    float S0, SA, SB, SC, SD;
    {
        float P08 = (__popc(t & 0x08) & 1) ? -1.f : 1.f;
        float P80 = (__popc(t & 0x80) & 1) ? -1.f : 1.f;
        float P48 = (__popc(t & 0x48) & 1) ? -1.f : 1.f;
        float PA0 = (__popc(t & 0xA0) & 1) ? -1.f : 1.f;
        float P58 = (__popc(t & 0x58) & 1) ? -1.f : 1.f;
        float PA4 = (__popc(t & 0xA4) & 1) ? -1.f : 1.f;
        float PA5 = (__popc(t & 0xA5) & 1) ? -1.f : 1.f;
        float P5A = (__popc(t & 0x5A) & 1) ? -1.f : 1.f;
        S0 = hw[0] * P08 + hw[1] * P80 + hw[2] * P48;     // no k dependence
        SA = hw[3] * P80 + hw[5] * PA0;                   // class k3
        SB = hw[4] * P48 + hw[6] * P58;                   // class k2
        SC = hw[7] * PA0 + hw[9] * PA4 + hw[11] * PA5;    // class k1^k3
        SD = hw[8] * P58 + hw[10] * P5A;                  // class k0^k2
    }

    const ulonglong2* g1 = gx;            // layer-1 tangents (wires 0..11)
    const ulonglong2* g2 = gx + 12;       // layer 2
    const ulonglong2* g3 = gx + 24;       // layer 3 (conjugated rot3~)
    const ulonglong2* d1 = dtab;          // layer-1 diagonals (3 windows x 16)
    const ulonglong2* d2 = dtab + 48;     // layer-2 diagonals

    // ======== P1: init + rot1(w0-3) + diag1 + stair1 store  [res 11-8] ====
    {
        u64 X[16], Y[16];
        int u = t ^ (t >> 1);             // u bit (11-w) = b_w for wires 5..11
        ulonglong2 p5 = vtab[(5 << 1) | ((u >> 6) & 1)];
        u64 PX = p5.x, PY = p5.y;
#pragma unroll
        for (int w = 6; w <= 11; w++) {
            ulonglong2 q = vtab[(w << 1) | ((u >> (11 - w)) & 1)];
            u64 nx = fma2(PX, q.x, neg2(mul2(PY, q.y)));
            u64 ny = fma2(PX, q.y, mul2(PY, q.x));
            PX = nx; PY = ny;
        }
        int t7 = (t >> 7) & 1;
        ulonglong2 q0 = vtab[(4 << 1) | t7];
        ulonglong2 q1 = vtab[(4 << 1) | (t7 ^ 1)];
        u64 R0X = fma2(PX, q0.x, neg2(mul2(PY, q0.y)));
        u64 R0Y = fma2(PX, q0.y, mul2(PY, q0.x));
        u64 R1X = fma2(PX, q1.x, neg2(mul2(PY, q1.y)));
        u64 R1Y = fma2(PX, q1.y, mul2(PY, q1.x));
        GX G0 = load_gx(g1);
#pragma unroll
        for (int j = 0; j < 8; j++) {     // build pair (j, j|8), rotate wire0
            ulonglong2 Fk0 = Ftab[j];
            u64 QX = (j & 1) ? R1X : R0X;
            u64 QY = (j & 1) ? R1Y : R0Y;
            X[j] = fma2(Fk0.x, QX, neg2(mul2(Fk0.y, QY)));
            Y[j] = fma2(Fk0.x, QY, mul2(Fk0.y, QX));
            ulonglong2 Fk1 = Ftab[j | 8];
            X[j | 8] = fma2(Fk1.x, QX, neg2(mul2(Fk1.y, QY)));
            Y[j | 8] = fma2(Fk1.x, QY, mul2(Fk1.y, QX));
            rxp(G0, X, Y, j, j | 8);
        }
        GX G1 = load_gx(g1 + 1); rotm<4, 4>(G1, X, Y);
        GX G2 = load_gx(g1 + 2); rotm<2, 2>(G2, X, Y);
        GX G3 = load_gx(g1 + 3); rotm<1, 1>(G3, X, Y);
#pragma unroll
        for (int k = 0; k < 16; k++) {    // diag1(A) + stair1 store
            diag1e(d1[k], X, Y, k);
            st[baseA8 ^ offkA(tau4(k))] = amp_pack(X[k], Y[k]);
        }
    }
    __syncthreads();

    // ======== P2: rot1(w4-7) + diag1 + stair1 + C34 fold  [res 7-4] ====
    {
        u64 X[16], Y[16];
        GX G4 = load_gx(g1 + 4);
#pragma unroll
        for (int j = 0; j < 8; j++) {
            amp_unpack(st[baseB8 ^ offkB(j)],     X[j],     Y[j]);
            amp_unpack(st[baseB8 ^ offkB(j | 8)], X[j | 8], Y[j | 8]);
            rxp(G4, X, Y, j, j | 8);
        }
        GX G5 = load_gx(g1 + 5); rotm<4, 4>(G5, X, Y);
        GX G6 = load_gx(g1 + 6); rotm<2, 2>(G6, X, Y);
        GX G7 = load_gx(g1 + 7); rotm<1, 1>(G7, X, Y);
#pragma unroll
        for (int k = 0; k < 16; k++) {
            diag1e(d1[16 + k], X, Y, k);
            st[baseBs8 ^ offkB(tau4(k))] = amp_pack(X[k], Y[k]);
        }
    }
    __syncthreads();

    // ======== P3: rot1(w8-10)+diag1+stair1+C78(in-reg)+rot2+diag2+rot3~ ====
    // (rot1(w11) folded into init)
    {
        u64 X[16], Y[16];
        GX G8 = load_gx(g1 + 8);
#pragma unroll
        for (int j = 0; j < 8; j++) {
            amp_unpack(st[baseC8 ^ j],       X[j],     Y[j]);
            amp_unpack(st[baseC8 ^ (j | 8)], X[j | 8], Y[j | 8]);
            rxp(G8, X, Y, j, j | 8);
        }
        GX G9  = load_gx(g1 + 9);  rotm<4, 4>(G9, X, Y);
        GX G10 = load_gx(g1 + 10); rotm<2, 2>(G10, X, Y);
#pragma unroll
        for (int k = 0; k < 16; k++) diag1e(d1[32 + k], X, Y, k);  // diag1(C)
        // rot2(w8-11) in final-label space: offsets tau4^-1(8,4,2,1)=12,6,3,1
        GX H8  = load_gx(g2 + 8);  rotm<12, 8>(H8, X, Y);
        GX H9  = load_gx(g2 + 9);  rotm<6, 4>(H9, X, Y);
        GX H10 = load_gx(g2 + 10); rotm<3, 2>(H10, X, Y);
        GX H11 = load_gx(g2 + 11); rotm<1, 1>(H11, X, Y);
#pragma unroll
        for (int k = 0; k < 16; k++) diag1e(d2[32 + (tau4(k) ^ cxC)], X, Y, k);
        // rot3~(w8..11): final masks {3,2},{2,1},{1,0},{0} -> orig 0xA,5,2,1
        GX J8  = load_gx(g3 + 8);  rotm<10, 8>(J8, X, Y);
        GX J9  = load_gx(g3 + 9);  rotm<5, 4>(J9, X, Y);
        GX J10 = load_gx(g3 + 10); rotm<2, 2>(J10, X, Y);
        GX J11 = load_gx(g3 + 11); rotm<1, 1>(J11, X, Y);
#pragma unroll
        for (int k = 0; k < 16; k++)
            st[baseC8 ^ tau4(k)] = amp_pack(X[k], Y[k]);
    }
    __syncthreads();

    // ======== P4: rot2(w4-7)+diag2+rot3~(w4-6)  [res 7-4] ====
    // load corrects P3's residual: true amp bits3-0 ^= 0xF when bit4(=k0)=1
    {
        u64 X[16], Y[16];
        GX H4 = load_gx(g2 + 4);
#pragma unroll
        for (int j = 0; j < 8; j++) {
            int fx = (j & 1) ? 0xF : 0;
            amp_unpack(st[baseB8 ^ offkB(j) ^ fx],       X[j],     Y[j]);
            amp_unpack(st[baseB8 ^ offkB(j | 8) ^ fx],   X[j | 8], Y[j | 8]);
            rxp(H4, X, Y, j, j | 8);
        }
        GX H5 = load_gx(g2 + 5); rotm<4, 4>(H5, X, Y);
        GX H6 = load_gx(g2 + 6); rotm<2, 2>(H6, X, Y);
        GX H7 = load_gx(g2 + 7); rotm<1, 1>(H7, X, Y);
#pragma unroll
        for (int k = 0; k < 16; k++) diag1e(d2[16 + k], X, Y, k);
        GX J4 = load_gx(g3 + 4); rotm<12, 8>(J4, X, Y);   // w4: bits{7,6}
        GX J5 = load_gx(g3 + 5); rotm<6, 4>(J5, X, Y);    // w5: bits{6,5}
        GX J6 = load_gx(g3 + 6); rotm<3, 2>(J6, X, Y);    // w6: bits{5,4}
#pragma unroll
        for (int k = 0; k < 16; k++)
            st[baseB8 ^ offkB(k)] = amp_pack(X[k], Y[k]); // canonical store
    }
    __syncthreads();

    // ======== P5: rot2(w0-3)+diag2+rot3~(w0-2)  [res 11-8] ====
    {
        u64 X[16], Y[16];
        GX H0 = load_gx(g2);
#pragma unroll
        for (int j = 0; j < 8; j++) {
            amp_unpack(st[baseA8 ^ offkA(j)],       X[j],     Y[j]);
            amp_unpack(st[baseA8 ^ offkA(j | 8)],   X[j | 8], Y[j | 8]);
            rxp(H0, X, Y, j, j | 8);
        }
        GX H1 = load_gx(g2 + 1); rotm<4, 4>(H1, X, Y);
        GX H2 = load_gx(g2 + 2); rotm<2, 2>(H2, X, Y);
        GX H3 = load_gx(g2 + 3); rotm<1, 1>(H3, X, Y);
#pragma unroll
        for (int k = 0; k < 16; k++) diag1e(d2[k], X, Y, k);
        GX J0 = load_gx(g3);     rotm<12, 8>(J0, X, Y);   // w0: bits{11,10}
        GX J1 = load_gx(g3 + 1); rotm<6, 4>(J1, X, Y);    // w1: bits{10,9}
        GX J2 = load_gx(g3 + 2); rotm<3, 2>(J2, X, Y);    // w2: bits{9,8}
#pragma unroll
        for (int k = 0; k < 16; k++)
            st[baseA8 ^ offkA(k)] = amp_pack(X[k], Y[k]);
    }
    __syncthreads();

    // ======== P6: rot3~(w3), rot3~(w7) + fused measurement  [res 8,7,4,3] ====
    float pacc[2] = {0.f, 0.f};
    {
        u64 X[16], Y[16];
#pragma unroll
        for (int k = 0; k < 16; k++)
            amp_unpack(st[base6 ^ offk6(k)], X[k], Y[k]);
        GX J3 = load_gx(g3 + 3); rotm<12, 8>(J3, X, Y);   // w3: bits{8,7}=k3,k2
        GX J7 = load_gx(g3 + 7); rotm<3, 2>(J7, X, Y);    // w7: bits{4,3}=k1,k0
#pragma unroll
        for (int k = 0; k < 16; k++) {
            float wl = S0
                + (((k >> 3) & 1) ? -SA : SA)
                + (((k >> 2) & 1) ? -SB : SB)
                + ((((k >> 1) ^ (k >> 3)) & 1) ? -SC : SC)
                + (((k ^ (k >> 2)) & 1) ? -SD : SD);
            u64 U = fma2(X[k], X[k], mul2(Y[k], Y[k]));
            float2 u = unpack2(U);
            pacc[0] = fmaf(u.x, wl, pacc[0]);
            pacc[1] = fmaf(u.y, wl, pacc[1]);
        }
    }

    // ---- reduce both samples; apply deferred layer-3 scale ----
    float p0 = pacc[0], p1 = pacc[1];
#pragma unroll
    for (int o = 16; o; o >>= 1) {
        p0 += __shfl_xor_sync(0xFFFFFFFFu, p0, o);
        p1 += __shfl_xor_sync(0xFFFFFFFFu, p1, o);
    }
    if ((t & 31) == 0) red[t >> 5] = make_float2(p0, p1);
    __syncthreads();
    if (t < 2) {
        float s = 0.f;
#pragma unroll
        for (int w = 0; w < 8; w++) s += (t == 0) ? red[w].x : red[w].y;
        out[2 * b + t] = s * a3[0] + head_b[0];
    }
}

extern "C" void kernel_launch(void* const* d_in, const int* in_sizes, int n_in,
                              void* d_out, int out_size)
{
    const float* inputs = (const float*)d_in[0];
    const float* params = (const float*)d_in[1];
    const float* head_w = (const float*)d_in[2];
    const float* head_b = (const float*)d_in[3];
    float* out = (float*)d_out;

    cudaFuncSetAttribute(qsim13_kernel, cudaFuncAttributeMaxDynamicSharedMemorySize, SMEM_BYTES);
    qsetup_kernel<<<1, 192>>>(params, head_w);           // batch-shared constants
    int B2 = out_size / 2;                               // two samples per block
    qsim13_kernel<<<B2, 256, SMEM_BYTES>>>(inputs, head_w, head_b, out);
}